// round 8
// baseline (speedup 1.0000x reference)
#include <cuda_runtime.h>
#include <cuda_fp16.h>
#include <stdint.h>

#define DD 128
#define NMAX 100000
#define EMAX 3200000
typedef unsigned long long u64;

// -------- device-global scratch --------
__device__ float  g_agg[(size_t)NMAX * DD];
__device__ float  g_h0 [(size_t)NMAX * DD];
__device__ float  g_h1 [(size_t)NMAX * DD];
__device__ __half g_h16[(size_t)NMAX * DD];
__device__ int    g_cnt [NMAX];
__device__ int    g_cur [NMAX];
__device__ int    g_incl[NMAX];
__device__ int    g_bsum[512];
__device__ int    g_rowptr[NMAX + 1];
__device__ int    g_csr [EMAX];

// ==================== conv16 + zero counters ====================
__global__ void conv16z_kernel(const float* __restrict__ src, __half* __restrict__ dst,
                               int* __restrict__ cnt, int* __restrict__ cur,
                               int total4, int n) {
    int i = blockIdx.x * blockDim.x + threadIdx.x;
    if (i < total4) {
        float4 v = __ldg((const float4*)src + i);
        __half2 a = __floats2half2_rn(v.x, v.y);
        __half2 b = __floats2half2_rn(v.z, v.w);
        *((uint2*)dst + i) = make_uint2(*(uint32_t*)&a, *(uint32_t*)&b);
    }
    if (i < n) { cnt[i] = 0; cur[i] = 0; }
}

// ==================== CSR build ====================
__global__ void deg_kernel(const int* __restrict__ dst, int* __restrict__ cnt, long long E) {
    long long e = (long long)blockIdx.x * blockDim.x + threadIdx.x;
    if (e < E) atomicAdd(&cnt[dst[e]], 1);
}

#define SB 256
__global__ void scan1(const int* __restrict__ cnt, int* __restrict__ incl,
                      int* __restrict__ bsum, int n) {
    __shared__ int sm[SB];
    int i = blockIdx.x * SB + threadIdx.x;
    int v = (i < n) ? cnt[i] : 0;
    sm[threadIdx.x] = v;
    __syncthreads();
    for (int off = 1; off < SB; off <<= 1) {
        int t = (threadIdx.x >= off) ? sm[threadIdx.x - off] : 0;
        __syncthreads();
        sm[threadIdx.x] += t;
        __syncthreads();
    }
    if (i < n) incl[i] = sm[threadIdx.x];
    if (threadIdx.x == SB - 1) bsum[blockIdx.x] = sm[SB - 1];
}

__global__ void scan2(int* __restrict__ bsum, int nb) {  // exclusive scan, nb <= 512
    __shared__ int sm[512];
    int v = ((int)threadIdx.x < nb) ? bsum[threadIdx.x] : 0;
    sm[threadIdx.x] = v;
    __syncthreads();
    for (int off = 1; off < 512; off <<= 1) {
        int t = (threadIdx.x >= off) ? sm[threadIdx.x - off] : 0;
        __syncthreads();
        sm[threadIdx.x] += t;
        __syncthreads();
    }
    if ((int)threadIdx.x < nb) bsum[threadIdx.x] = sm[threadIdx.x] - v;
}

__global__ void scan3(const int* __restrict__ incl, const int* __restrict__ cnt,
                      const int* __restrict__ bsum, int* __restrict__ rowptr,
                      int n, int E) {
    int i = blockIdx.x * 256 + threadIdx.x;
    if (i < n) rowptr[i] = incl[i] - cnt[i] + bsum[i / SB];
    if (i == 0) rowptr[n] = E;
}

__global__ void place_kernel(const int* __restrict__ ei, const int* __restrict__ rowptr,
                             int* __restrict__ cur, int* __restrict__ csr, long long E) {
    long long e = (long long)blockIdx.x * blockDim.x + threadIdx.x;
    if (e < E) {
        int s = ei[e];
        int d = ei[E + e];
        int pos = rowptr[d] + atomicAdd(&cur[d], 1);
        csr[pos] = s;
    }
}

// ==================== f32x2 helpers ====================
__device__ __forceinline__ void fma2(u64& d, u64 a, u64 b) {
    asm("fma.rn.f32x2 %0, %1, %2, %0;" : "+l"(d) : "l"(a), "l"(b));
}
__device__ __forceinline__ u64 dup2(float x) {
    u64 r;
    asm("mov.b64 %0, {%1, %1};" : "=l"(r) : "r"(__float_as_uint(x)));
    return r;
}
__device__ __forceinline__ void unpk(float& lo, float& hi, u64 v) {
    unsigned a, b;
    asm("mov.b64 {%0, %1}, %2;" : "=r"(a), "=r"(b) : "l"(v));
    lo = __uint_as_float(a); hi = __uint_as_float(b);
}

// ==================== K=128 GEMM tile body ====================
// PHASE 0: out_tile = A @ W^T + bias           (partial, no relu/h16)
// PHASE 1: out_tile = act(A @ W^T + out_tile)  (reads partial in-place; emits h16)
// Tile: 64 rows x 128 cols, 256 threads, smem = Wt[128][128] + As[128][64] = 96KB.
#define GEMM_SMEM ((128 * 128 + 128 * 64) * sizeof(float))

template<int PHASE>
__device__ __forceinline__ void gemm128(const float* __restrict__ A,
                                        const float* __restrict__ W,
                                        const float* __restrict__ bias,
                                        float* __restrict__ out,
                                        __half* __restrict__ h16out,
                                        int n, int relu, int tile, float* sm) {
    float* Wt = sm;                 // [128][128] : Wt[k][j] = W[j][k]
    float* As = sm + 128 * 128;     // [128][64]  : As[k][r]
    int tid = threadIdx.x;
    int row0 = tile * 64;

    #pragma unroll
    for (int i = 0; i < 16; i++) {
        int fidx = i * 256 + tid;          // 0..4095
        int j  = fidx % 128;
        int k  = (fidx / 128) * 4;         // 0..124
        float4 v = __ldg((const float4*)(W + j * DD + k));
        Wt[(k + 0) * 128 + j] = v.x;
        Wt[(k + 1) * 128 + j] = v.y;
        Wt[(k + 2) * 128 + j] = v.z;
        Wt[(k + 3) * 128 + j] = v.w;
    }
    #pragma unroll
    for (int i = 0; i < 8; i++) {
        int fidx = i * 256 + tid;          // 0..2047
        int r  = fidx % 64;
        int k  = (fidx / 64) * 4;
        int row = row0 + r;
        float4 v = make_float4(0.f, 0.f, 0.f, 0.f);
        if (row < n) v = __ldg((const float4*)(A + (size_t)row * DD + k));
        As[(k + 0) * 64 + r] = v.x;
        As[(k + 1) * 64 + r] = v.y;
        As[(k + 2) * 64 + r] = v.z;
        As[(k + 3) * 64 + r] = v.w;
    }
    __syncthreads();

    int tx = tid & 31;
    int ty = tid >> 5;        // 0..7, rows ty*8 .. ty*8+7
    int col = tx * 4;

    u64 acc2[4][4];
    #pragma unroll
    for (int p = 0; p < 4; p++)
        #pragma unroll
        for (int c = 0; c < 4; c++) acc2[p][c] = 0ull;

    #pragma unroll 4
    for (int k = 0; k < 128; k++) {
        float4 w = *(const float4*)(Wt + k * 128 + col);
        u64 wp0 = dup2(w.x), wp1 = dup2(w.y), wp2 = dup2(w.z), wp3 = dup2(w.w);
        ulonglong2 q0 = *(const ulonglong2*)(As + k * 64 + ty * 8);
        ulonglong2 q1 = *(const ulonglong2*)(As + k * 64 + ty * 8 + 4);
        u64 pr[4] = {q0.x, q0.y, q1.x, q1.y};
        #pragma unroll
        for (int p = 0; p < 4; p++) {
            fma2(acc2[p][0], pr[p], wp0);
            fma2(acc2[p][1], pr[p], wp1);
            fma2(acc2[p][2], pr[p], wp2);
            fma2(acc2[p][3], pr[p], wp3);
        }
    }

    float4 bv = make_float4(0.f, 0.f, 0.f, 0.f);
    if (PHASE == 0) bv = __ldg((const float4*)(bias + col));
    #pragma unroll
    for (int p = 0; p < 4; p++) {
        float lo[4], hi[4];
        #pragma unroll
        for (int c = 0; c < 4; c++) unpk(lo[c], hi[c], acc2[p][c]);
        int row = row0 + ty * 8 + 2 * p;
        #pragma unroll
        for (int half = 0; half < 2; half++) {
            int rr = row + half;
            if (rr >= n) continue;
            float* src = half ? hi : lo;
            float4 o;
            if (PHASE == 0) {
                o = make_float4(src[0] + bv.x, src[1] + bv.y, src[2] + bv.z, src[3] + bv.w);
            } else {
                float4 pv = *(const float4*)(out + (size_t)rr * DD + col);
                o = make_float4(src[0] + pv.x, src[1] + pv.y, src[2] + pv.z, src[3] + pv.w);
                if (relu) { o.x = fmaxf(o.x, 0.f); o.y = fmaxf(o.y, 0.f);
                            o.z = fmaxf(o.z, 0.f); o.w = fmaxf(o.w, 0.f); }
            }
            *(float4*)(out + (size_t)rr * DD + col) = o;
            if (PHASE == 1 && h16out) {
                __half2 a = __floats2half2_rn(o.x, o.y);
                __half2 b = __floats2half2_rn(o.z, o.w);
                *(uint2*)(h16out + (size_t)rr * DD + col) =
                    make_uint2(*(uint32_t*)&a, *(uint32_t*)&b);
            }
        }
    }
}

// ==================== agg body (warp per dst node, fp16 gather) ====================
__device__ __forceinline__ void agg_body(const __half* __restrict__ h16,
                                         const int* __restrict__ rowptr,
                                         const int* __restrict__ csr,
                                         float* __restrict__ agg, int n, int abid) {
    int d = abid * 8 + ((int)threadIdx.x >> 5);
    int lane = threadIdx.x & 31;
    if (d >= n) return;
    int beg = __ldg(&rowptr[d]);
    int end = __ldg(&rowptr[d + 1]);
    float4 acc = make_float4(0.f, 0.f, 0.f, 0.f);
    for (int j = beg; j < end; j += 32) {
        int cnt = min(32, end - j);
        int s = (lane < cnt) ? __ldg(&csr[j + lane]) : 0;
        #pragma unroll 4
        for (int t = 0; t < cnt; t++) {
            int ss = __shfl_sync(0xffffffffu, s, t);
            uint2 raw = __ldg((const uint2*)(h16 + (size_t)ss * DD) + lane);
            __half2 a = *(__half2*)&raw.x;
            __half2 b = *(__half2*)&raw.y;
            float2 fa = __half22float2(a);
            float2 fb = __half22float2(b);
            acc.x += fa.x; acc.y += fa.y; acc.z += fb.x; acc.w += fb.y;
        }
    }
    float inv = 1.0f / fmaxf((float)(end - beg), 1.0f);
    acc.x *= inv; acc.y *= inv; acc.z *= inv; acc.w *= inv;
    *((float4*)(agg + (size_t)d * DD) + lane) = acc;
}

// ==================== combined: agg (8/9 of blocks) + hgemm partial (1/9) ====================
__global__ void __launch_bounds__(256, 2)
combined_kernel(const __half* __restrict__ h16, const int* __restrict__ rowptr,
                const int* __restrict__ csr, float* __restrict__ agg,
                const float* __restrict__ h, const float* __restrict__ Wr,
                const float* __restrict__ bias, float* __restrict__ outp,
                int n, int ntiles) {
    extern __shared__ float sm[];
    int bid = blockIdx.x;
    int g = bid / 9, rem = bid - g * 9;
    if (rem == 0 && g < ntiles) {
        gemm128<0>(h, Wr, bias, outp, (__half*)0, n, 0, g, sm);
        return;
    }
    int abid = bid - g - 1;   // g < ntiles always given grid = 9*ntiles
    agg_body(h16, rowptr, csr, agg, n, abid);
}

// ==================== mgemm: out = act(partial + mean @ Wl^T) ====================
__global__ void __launch_bounds__(256, 2)
mgemm_kernel(const float* __restrict__ mean, const float* __restrict__ Wl,
             float* __restrict__ out, __half* __restrict__ h16out, int n, int relu) {
    extern __shared__ float sm[];
    gemm128<1>(mean, Wl, (const float*)0, out, h16out, n, relu, blockIdx.x, sm);
}

// ==================== launch ====================
extern "C" void kernel_launch(void* const* d_in, const int* in_sizes, int n_in,
                              void* d_out, int out_size) {
    const float* x   = (const float*)d_in[0];
    const int*   ei  = (const int*)d_in[1];     // int32
    const float* W1l = (const float*)d_in[2];
    const float* W1r = (const float*)d_in[3];
    const float* W2l = (const float*)d_in[4];
    const float* W2r = (const float*)d_in[5];
    const float* W3l = (const float*)d_in[6];
    const float* W3r = (const float*)d_in[7];
    const float* b1  = (const float*)d_in[8];
    const float* b2  = (const float*)d_in[9];
    const float* b3  = (const float*)d_in[10];
    float* out = (float*)d_out;

    int n = in_sizes[0] / DD;
    long long E = (long long)in_sizes[1] / 2;

    float *agg, *h0, *h1;
    __half* h16;
    int *cnt, *cur, *incl, *bsum, *rowptr, *csr;
    cudaGetSymbolAddress((void**)&agg,    g_agg);
    cudaGetSymbolAddress((void**)&h0,     g_h0);
    cudaGetSymbolAddress((void**)&h1,     g_h1);
    cudaGetSymbolAddress((void**)&h16,    g_h16);
    cudaGetSymbolAddress((void**)&cnt,    g_cnt);
    cudaGetSymbolAddress((void**)&cur,    g_cur);
    cudaGetSymbolAddress((void**)&incl,   g_incl);
    cudaGetSymbolAddress((void**)&bsum,   g_bsum);
    cudaGetSymbolAddress((void**)&rowptr, g_rowptr);
    cudaGetSymbolAddress((void**)&csr,    g_csr);

    cudaFuncSetAttribute(combined_kernel, cudaFuncAttributeMaxDynamicSharedMemorySize,
                         (int)GEMM_SMEM);
    cudaFuncSetAttribute(mgemm_kernel, cudaFuncAttributeMaxDynamicSharedMemorySize,
                         (int)GEMM_SMEM);

    unsigned eblocks = (unsigned)((E + 255) / 256);
    int total4 = n * DD / 4;
    int nb = (n + SB - 1) / SB;

    conv16z_kernel<<<(total4 + 255) / 256, 256>>>(x, h16, cnt, cur, total4, n);
    deg_kernel<<<eblocks, 256>>>(ei + E, cnt, E);
    scan1<<<nb, SB>>>(cnt, incl, bsum, n);
    scan2<<<1, 512>>>(bsum, nb);
    scan3<<<(n + 255) / 256, 256>>>(incl, cnt, bsum, rowptr, n, (int)E);
    place_kernel<<<eblocks, 256>>>(ei, rowptr, cur, csr, E);

    int ntiles = (n + 63) / 64;
    int cgrid  = 9 * ntiles;

    // Layer 1
    combined_kernel<<<cgrid, 256, GEMM_SMEM>>>(h16, rowptr, csr, agg, x, W1r, b1, h0, n, ntiles);
    mgemm_kernel<<<ntiles, 256, GEMM_SMEM>>>(agg, W1l, h0, h16, n, 1);
    // Layer 2
    combined_kernel<<<cgrid, 256, GEMM_SMEM>>>(h16, rowptr, csr, agg, h0, W2r, b2, h1, n, ntiles);
    mgemm_kernel<<<ntiles, 256, GEMM_SMEM>>>(agg, W2l, h1, h16, n, 1);
    // Layer 3
    combined_kernel<<<cgrid, 256, GEMM_SMEM>>>(h16, rowptr, csr, agg, h1, W3r, b3, out, n, ntiles);
    mgemm_kernel<<<ntiles, 256, GEMM_SMEM>>>(agg, W3l, out, (__half*)0, n, 0);
}

// round 9
// speedup vs baseline: 1.6464x; 1.6464x over previous
#include <cuda_runtime.h>
#include <cuda_fp16.h>
#include <stdint.h>

#define DD 128
#define NMAX 100000
#define EMAX 3200000
typedef unsigned long long u64;

// -------- device-global scratch --------
__device__ float  g_agg[(size_t)NMAX * DD];
__device__ float  g_h0 [(size_t)NMAX * DD];
__device__ float  g_h1 [(size_t)NMAX * DD];
__device__ __half g_h16[(size_t)NMAX * DD];
__device__ int    g_cnt [NMAX];
__device__ int    g_cur [NMAX];
__device__ int    g_incl[NMAX];
__device__ int    g_bsum[512];
__device__ int    g_rowptr[NMAX + 1];
__device__ int    g_csr [EMAX];

// ==================== conv16 + zero counters ====================
__global__ void conv16z_kernel(const float* __restrict__ src, __half* __restrict__ dst,
                               int* __restrict__ cnt, int* __restrict__ cur,
                               int total4, int n) {
    int i = blockIdx.x * blockDim.x + threadIdx.x;
    if (i < total4) {
        float4 v = __ldg((const float4*)src + i);
        __half2 a = __floats2half2_rn(v.x, v.y);
        __half2 b = __floats2half2_rn(v.z, v.w);
        *((uint2*)dst + i) = make_uint2(*(uint32_t*)&a, *(uint32_t*)&b);
    }
    if (i < n) { cnt[i] = 0; cur[i] = 0; }
}

// ==================== CSR build ====================
__global__ void deg_kernel(const int* __restrict__ dst, int* __restrict__ cnt, long long E) {
    long long e = (long long)blockIdx.x * blockDim.x + threadIdx.x;
    if (e < E) atomicAdd(&cnt[dst[e]], 1);
}

#define SB 256
__global__ void scan1(const int* __restrict__ cnt, int* __restrict__ incl,
                      int* __restrict__ bsum, int n) {
    __shared__ int sm[SB];
    int i = blockIdx.x * SB + threadIdx.x;
    int v = (i < n) ? cnt[i] : 0;
    sm[threadIdx.x] = v;
    __syncthreads();
    for (int off = 1; off < SB; off <<= 1) {
        int t = (threadIdx.x >= off) ? sm[threadIdx.x - off] : 0;
        __syncthreads();
        sm[threadIdx.x] += t;
        __syncthreads();
    }
    if (i < n) incl[i] = sm[threadIdx.x];
    if (threadIdx.x == SB - 1) bsum[blockIdx.x] = sm[SB - 1];
}

__global__ void scan2(int* __restrict__ bsum, int nb) {
    __shared__ int sm[512];
    int v = ((int)threadIdx.x < nb) ? bsum[threadIdx.x] : 0;
    sm[threadIdx.x] = v;
    __syncthreads();
    for (int off = 1; off < 512; off <<= 1) {
        int t = (threadIdx.x >= off) ? sm[threadIdx.x - off] : 0;
        __syncthreads();
        sm[threadIdx.x] += t;
        __syncthreads();
    }
    if ((int)threadIdx.x < nb) bsum[threadIdx.x] = sm[threadIdx.x] - v;
}

__global__ void scan3(const int* __restrict__ incl, const int* __restrict__ cnt,
                      const int* __restrict__ bsum, int* __restrict__ rowptr,
                      int n, int E) {
    int i = blockIdx.x * 256 + threadIdx.x;
    if (i < n) rowptr[i] = incl[i] - cnt[i] + bsum[i / SB];
    if (i == 0) rowptr[n] = E;
}

__global__ void place_kernel(const int* __restrict__ ei, const int* __restrict__ rowptr,
                             int* __restrict__ cur, int* __restrict__ csr, long long E) {
    long long e = (long long)blockIdx.x * blockDim.x + threadIdx.x;
    if (e < E) {
        int s = ei[e];
        int d = ei[E + e];
        int pos = rowptr[d] + atomicAdd(&cur[d], 1);
        csr[pos] = s;
    }
}

// ==================== mean aggregation (R5 form: warp per dst node) ====================
__global__ void agg_kernel(const __half* __restrict__ h16, const int* __restrict__ rowptr,
                           const int* __restrict__ csr, float* __restrict__ agg, int n) {
    int d = blockIdx.x * (blockDim.x >> 5) + (threadIdx.x >> 5);
    int lane = threadIdx.x & 31;
    if (d >= n) return;
    int beg = __ldg(&rowptr[d]);
    int end = __ldg(&rowptr[d + 1]);
    float4 acc = make_float4(0.f, 0.f, 0.f, 0.f);
    for (int j = beg; j < end; j += 32) {
        int cnt = min(32, end - j);
        int s = (lane < cnt) ? __ldg(&csr[j + lane]) : 0;
        #pragma unroll 4
        for (int t = 0; t < cnt; t++) {
            int ss = __shfl_sync(0xffffffffu, s, t);
            uint2 raw = __ldg((const uint2*)(h16 + (size_t)ss * DD) + lane);
            __half2 a = *(__half2*)&raw.x;
            __half2 b = *(__half2*)&raw.y;
            float2 fa = __half22float2(a);
            float2 fb = __half22float2(b);
            acc.x += fa.x; acc.y += fa.y; acc.z += fb.x; acc.w += fb.y;
        }
    }
    float inv = 1.0f / fmaxf((float)(end - beg), 1.0f);
    acc.x *= inv; acc.y *= inv; acc.z *= inv; acc.w *= inv;
    *((float4*)(agg + (size_t)d * DD) + lane) = acc;
}

// ==================== f32x2 helpers ====================
__device__ __forceinline__ void fma2(u64& d, u64 a, u64 b) {
    asm("fma.rn.f32x2 %0, %1, %2, %0;" : "+l"(d) : "l"(a), "l"(b));
}
__device__ __forceinline__ u64 dup2(float x) {
    u64 r;
    asm("mov.b64 %0, {%1, %1};" : "=l"(r) : "r"(__float_as_uint(x)));
    return r;
}
__device__ __forceinline__ void unpk(float& lo, float& hi, u64 v) {
    unsigned a, b;
    asm("mov.b64 {%0, %1}, %2;" : "=r"(a), "=r"(b) : "l"(v));
    lo = __uint_as_float(a); hi = __uint_as_float(b);
}

// ==================== fused SAGE GEMM (8x8 blocking, conflict-free) ====================
// out = relu?(mean @ Wl^T + h @ Wr^T + b); tile 128 rows x 128 cols, 256 threads.
// K=256 via two As passes (mean, then h) over resident Wt[256][128].
// Thread (tx=tid&15, ty=tid>>4): rows ty*8..+7, cols {tx*4..+3} U {64+tx*4..+3}.
#define GEMM_SMEM ((256 * 128 + 128 * 128) * sizeof(float))   // 128KB Wt + 64KB As = 192KB

__global__ void __launch_bounds__(256, 1)
sage_gemm(const float* __restrict__ mean, const float* __restrict__ h,
          const float* __restrict__ Wl, const float* __restrict__ Wr,
          const float* __restrict__ bias, float* __restrict__ out,
          __half* __restrict__ h16out, int n, int relu) {
    extern __shared__ float sm[];
    float* Wt = sm;                 // [256][128] : Wt[kk][j] = (kk<128? Wl[j][kk] : Wr[j][kk-128])
    float* As = sm + 256 * 128;     // [128][64.. no: [128][128] : As[k][r]

    int tid = threadIdx.x;
    int row0 = blockIdx.x * 128;

    // Load both weights transposed: 8192 float4, 32 per thread
    #pragma unroll
    for (int i = 0; i < 32; i++) {
        int fidx = i * 256 + tid;          // 0..8191
        int j  = fidx & 127;
        int kk = (fidx >> 7) << 2;         // 0..252
        float4 v;
        if (kk < 128) v = __ldg((const float4*)(Wl + j * DD + kk));
        else          v = __ldg((const float4*)(Wr + j * DD + (kk - 128)));
        Wt[(kk + 0) * 128 + j] = v.x;
        Wt[(kk + 1) * 128 + j] = v.y;
        Wt[(kk + 2) * 128 + j] = v.z;
        Wt[(kk + 3) * 128 + j] = v.w;
    }

    int tx = tid & 15;        // col groups: tx*4 and 64+tx*4
    int ty = tid >> 4;        // rows ty*8 .. ty*8+7

    u64 acc2[4][8];           // [row-pair p][col c: 0-3 -> tx*4+c, 4-7 -> 64+tx*4+(c-4)]
    #pragma unroll
    for (int p = 0; p < 4; p++)
        #pragma unroll
        for (int c = 0; c < 8; c++) acc2[p][c] = 0ull;

    #pragma unroll
    for (int pass = 0; pass < 2; pass++) {
        const float* A = pass ? h : mean;
        // Load A tile transposed: As[k][r], 4096 float4, 16 per thread
        __syncthreads();
        #pragma unroll
        for (int i = 0; i < 16; i++) {
            int fidx = i * 256 + tid;      // 0..4095
            int r = fidx & 127;
            int k = (fidx >> 7) << 2;      // 0..124
            int row = row0 + r;
            float4 v = make_float4(0.f, 0.f, 0.f, 0.f);
            if (row < n) v = __ldg((const float4*)(A + (size_t)row * DD + k));
            As[(k + 0) * 128 + r] = v.x;
            As[(k + 1) * 128 + r] = v.y;
            As[(k + 2) * 128 + r] = v.z;
            As[(k + 3) * 128 + r] = v.w;
        }
        __syncthreads();

        const float* WtP = Wt + pass * 128 * 128;
        #pragma unroll 4
        for (int k = 0; k < 128; k++) {
            float4 w0 = *(const float4*)(WtP + k * 128 + tx * 4);
            float4 w1 = *(const float4*)(WtP + k * 128 + 64 + tx * 4);
            u64 wp[8];
            wp[0] = dup2(w0.x); wp[1] = dup2(w0.y); wp[2] = dup2(w0.z); wp[3] = dup2(w0.w);
            wp[4] = dup2(w1.x); wp[5] = dup2(w1.y); wp[6] = dup2(w1.z); wp[7] = dup2(w1.w);
            ulonglong2 q0 = *(const ulonglong2*)(As + k * 128 + ty * 8);
            ulonglong2 q1 = *(const ulonglong2*)(As + k * 128 + ty * 8 + 4);
            u64 pr[4] = {q0.x, q0.y, q1.x, q1.y};
            #pragma unroll
            for (int p = 0; p < 4; p++) {
                #pragma unroll
                for (int c = 0; c < 8; c++) fma2(acc2[p][c], pr[p], wp[c]);
            }
        }
    }

    float4 bv0 = __ldg((const float4*)(bias + tx * 4));
    float4 bv1 = __ldg((const float4*)(bias + 64 + tx * 4));
    #pragma unroll
    for (int p = 0; p < 4; p++) {
        float lo[8], hi[8];
        #pragma unroll
        for (int c = 0; c < 8; c++) unpk(lo[c], hi[c], acc2[p][c]);
        #pragma unroll
        for (int half = 0; half < 2; half++) {
            int rr = row0 + ty * 8 + 2 * p + half;
            if (rr >= n) continue;
            float* src = half ? hi : lo;
            float4 o0 = make_float4(src[0] + bv0.x, src[1] + bv0.y, src[2] + bv0.z, src[3] + bv0.w);
            float4 o1 = make_float4(src[4] + bv1.x, src[5] + bv1.y, src[6] + bv1.z, src[7] + bv1.w);
            if (relu) {
                o0.x = fmaxf(o0.x, 0.f); o0.y = fmaxf(o0.y, 0.f);
                o0.z = fmaxf(o0.z, 0.f); o0.w = fmaxf(o0.w, 0.f);
                o1.x = fmaxf(o1.x, 0.f); o1.y = fmaxf(o1.y, 0.f);
                o1.z = fmaxf(o1.z, 0.f); o1.w = fmaxf(o1.w, 0.f);
            }
            *(float4*)(out + (size_t)rr * DD + tx * 4)      = o0;
            *(float4*)(out + (size_t)rr * DD + 64 + tx * 4) = o1;
            if (h16out) {
                __half2 a0 = __floats2half2_rn(o0.x, o0.y);
                __half2 b0 = __floats2half2_rn(o0.z, o0.w);
                __half2 a1 = __floats2half2_rn(o1.x, o1.y);
                __half2 b1 = __floats2half2_rn(o1.z, o1.w);
                *(uint2*)(h16out + (size_t)rr * DD + tx * 4) =
                    make_uint2(*(uint32_t*)&a0, *(uint32_t*)&b0);
                *(uint2*)(h16out + (size_t)rr * DD + 64 + tx * 4) =
                    make_uint2(*(uint32_t*)&a1, *(uint32_t*)&b1);
            }
        }
    }
}

// ==================== launch ====================
extern "C" void kernel_launch(void* const* d_in, const int* in_sizes, int n_in,
                              void* d_out, int out_size) {
    const float* x   = (const float*)d_in[0];
    const int*   ei  = (const int*)d_in[1];     // int32
    const float* W1l = (const float*)d_in[2];
    const float* W1r = (const float*)d_in[3];
    const float* W2l = (const float*)d_in[4];
    const float* W2r = (const float*)d_in[5];
    const float* W3l = (const float*)d_in[6];
    const float* W3r = (const float*)d_in[7];
    const float* b1  = (const float*)d_in[8];
    const float* b2  = (const float*)d_in[9];
    const float* b3  = (const float*)d_in[10];
    float* out = (float*)d_out;

    int n = in_sizes[0] / DD;
    long long E = (long long)in_sizes[1] / 2;

    float *agg, *h0, *h1;
    __half* h16;
    int *cnt, *cur, *incl, *bsum, *rowptr, *csr;
    cudaGetSymbolAddress((void**)&agg,    g_agg);
    cudaGetSymbolAddress((void**)&h0,     g_h0);
    cudaGetSymbolAddress((void**)&h1,     g_h1);
    cudaGetSymbolAddress((void**)&h16,    g_h16);
    cudaGetSymbolAddress((void**)&cnt,    g_cnt);
    cudaGetSymbolAddress((void**)&cur,    g_cur);
    cudaGetSymbolAddress((void**)&incl,   g_incl);
    cudaGetSymbolAddress((void**)&bsum,   g_bsum);
    cudaGetSymbolAddress((void**)&rowptr, g_rowptr);
    cudaGetSymbolAddress((void**)&csr,    g_csr);

    cudaFuncSetAttribute(sage_gemm, cudaFuncAttributeMaxDynamicSharedMemorySize,
                         (int)GEMM_SMEM);

    unsigned eblocks = (unsigned)((E + 255) / 256);
    int total4 = n * DD / 4;
    int nb = (n + SB - 1) / SB;

    conv16z_kernel<<<(total4 + 255) / 256, 256>>>(x, h16, cnt, cur, total4, n);
    deg_kernel<<<eblocks, 256>>>(ei + E, cnt, E);
    scan1<<<nb, SB>>>(cnt, incl, bsum, n);
    scan2<<<1, 512>>>(bsum, nb);
    scan3<<<(n + 255) / 256, 256>>>(incl, cnt, bsum, rowptr, n, (int)E);
    place_kernel<<<eblocks, 256>>>(ei, rowptr, cur, csr, E);

    int agg_blocks  = (n + 7) / 8;          // warp per node
    int gemm_blocks = (n + 127) / 128;

    // Layer 1
    agg_kernel<<<agg_blocks, 256>>>(h16, rowptr, csr, agg, n);
    sage_gemm<<<gemm_blocks, 256, GEMM_SMEM>>>(agg, x, W1l, W1r, b1, h0, h16, n, 1);
    // Layer 2
    agg_kernel<<<agg_blocks, 256>>>(h16, rowptr, csr, agg, n);
    sage_gemm<<<gemm_blocks, 256, GEMM_SMEM>>>(agg, h0, W2l, W2r, b2, h1, h16, n, 1);
    // Layer 3
    agg_kernel<<<agg_blocks, 256>>>(h16, rowptr, csr, agg, n);
    sage_gemm<<<gemm_blocks, 256, GEMM_SMEM>>>(agg, h1, W3l, W3r, b3, out, (__half*)0, n, 0);
}

// round 10
// speedup vs baseline: 1.6597x; 1.0081x over previous
#include <cuda_runtime.h>
#include <cuda_fp16.h>
#include <stdint.h>

#define DD 128
#define NMAX 100000
#define EMAX 3200000
typedef unsigned long long u64;

// -------- device-global scratch --------
__device__ float  g_agg[(size_t)NMAX * DD];
__device__ float  g_h0 [(size_t)NMAX * DD];
__device__ float  g_h1 [(size_t)NMAX * DD];
__device__ __half g_h16[(size_t)NMAX * DD];
__device__ int    g_cnt [NMAX];
__device__ int    g_cur [NMAX];
__device__ int    g_incl[NMAX];
__device__ int    g_bsum[512];
__device__ int    g_rowptr[NMAX + 1];
__device__ int    g_csr [EMAX];

// ==================== conv16 + zero counters ====================
__global__ void conv16z_kernel(const float* __restrict__ src, __half* __restrict__ dst,
                               int* __restrict__ cnt, int* __restrict__ cur,
                               int total4, int n) {
    int i = blockIdx.x * blockDim.x + threadIdx.x;
    if (i < total4) {
        float4 v = __ldg((const float4*)src + i);
        __half2 a = __floats2half2_rn(v.x, v.y);
        __half2 b = __floats2half2_rn(v.z, v.w);
        *((uint2*)dst + i) = make_uint2(*(uint32_t*)&a, *(uint32_t*)&b);
    }
    if (i < n) { cnt[i] = 0; cur[i] = 0; }
}

// ==================== CSR build ====================
__global__ void deg_kernel(const int* __restrict__ dst, int* __restrict__ cnt, long long E) {
    long long e = (long long)blockIdx.x * blockDim.x + threadIdx.x;
    if (e < E) atomicAdd(&cnt[dst[e]], 1);
}

#define SB 256
__global__ void scan1(const int* __restrict__ cnt, int* __restrict__ incl,
                      int* __restrict__ bsum, int n) {
    __shared__ int sm[SB];
    int i = blockIdx.x * SB + threadIdx.x;
    int v = (i < n) ? cnt[i] : 0;
    sm[threadIdx.x] = v;
    __syncthreads();
    for (int off = 1; off < SB; off <<= 1) {
        int t = (threadIdx.x >= off) ? sm[threadIdx.x - off] : 0;
        __syncthreads();
        sm[threadIdx.x] += t;
        __syncthreads();
    }
    if (i < n) incl[i] = sm[threadIdx.x];
    if (threadIdx.x == SB - 1) bsum[blockIdx.x] = sm[SB - 1];
}

__global__ void scan2(int* __restrict__ bsum, int nb) {
    __shared__ int sm[512];
    int v = ((int)threadIdx.x < nb) ? bsum[threadIdx.x] : 0;
    sm[threadIdx.x] = v;
    __syncthreads();
    for (int off = 1; off < 512; off <<= 1) {
        int t = (threadIdx.x >= off) ? sm[threadIdx.x - off] : 0;
        __syncthreads();
        sm[threadIdx.x] += t;
        __syncthreads();
    }
    if ((int)threadIdx.x < nb) bsum[threadIdx.x] = sm[threadIdx.x] - v;
}

__global__ void scan3(const int* __restrict__ incl, const int* __restrict__ cnt,
                      const int* __restrict__ bsum, int* __restrict__ rowptr,
                      int n, int E) {
    int i = blockIdx.x * 256 + threadIdx.x;
    if (i < n) rowptr[i] = incl[i] - cnt[i] + bsum[i / SB];
    if (i == 0) rowptr[n] = E;
}

__global__ void place_kernel(const int* __restrict__ ei, const int* __restrict__ rowptr,
                             int* __restrict__ cur, int* __restrict__ csr, long long E) {
    long long e = (long long)blockIdx.x * blockDim.x + threadIdx.x;
    if (e < E) {
        int s = ei[e];
        int d = ei[E + e];
        int pos = rowptr[d] + atomicAdd(&cur[d], 1);
        csr[pos] = s;
    }
}

// ==================== mean aggregation ====================
// Warp per dst node; 2 edges per iteration: half-warp h handles edge 2t+h,
// 16 lanes x uint4(16B) = full 256B fp16 row. Pair loop is predication-free;
// odd remainder edge handled once by half 0. Cross-half reduce at the end.
__global__ void agg_kernel(const __half* __restrict__ h16, const int* __restrict__ rowptr,
                           const int* __restrict__ csr, float* __restrict__ agg, int n) {
    int d = blockIdx.x * (blockDim.x >> 5) + (threadIdx.x >> 5);
    int lane = threadIdx.x & 31;
    if (d >= n) return;
    int beg = __ldg(&rowptr[d]);
    int end = __ldg(&rowptr[d + 1]);
    int half = lane >> 4;
    int hl   = lane & 15;     // feature dims [8*hl .. 8*hl+7]

    float acc[8];
    #pragma unroll
    for (int q = 0; q < 8; q++) acc[q] = 0.f;

    for (int j = beg; j < end; j += 32) {
        int cnt = min(32, end - j);
        int s = (lane < cnt) ? __ldg(&csr[j + lane]) : 0;
        int npair = cnt >> 1;
        #pragma unroll 4
        for (int t = 0; t < npair; t++) {
            int ss = __shfl_sync(0xffffffffu, s, 2 * t + half);
            uint4 raw = __ldg((const uint4*)(h16 + (size_t)ss * DD) + hl);
            const __half2* hp = (const __half2*)&raw;
            #pragma unroll
            for (int q = 0; q < 4; q++) {
                float2 f = __half22float2(hp[q]);
                acc[2 * q]     += f.x;
                acc[2 * q + 1] += f.y;
            }
        }
        if (cnt & 1) {   // warp-uniform; last edge processed by half 0 only
            int ss = __shfl_sync(0xffffffffu, s, cnt - 1);
            if (half == 0) {
                uint4 raw = __ldg((const uint4*)(h16 + (size_t)ss * DD) + hl);
                const __half2* hp = (const __half2*)&raw;
                #pragma unroll
                for (int q = 0; q < 4; q++) {
                    float2 f = __half22float2(hp[q]);
                    acc[2 * q]     += f.x;
                    acc[2 * q + 1] += f.y;
                }
            }
        }
    }
    #pragma unroll
    for (int q = 0; q < 8; q++) acc[q] += __shfl_xor_sync(0xffffffffu, acc[q], 16);

    if (half == 0) {
        float inv = 1.0f / fmaxf((float)(end - beg), 1.0f);
        float4 v0 = make_float4(acc[0] * inv, acc[1] * inv, acc[2] * inv, acc[3] * inv);
        float4 v1 = make_float4(acc[4] * inv, acc[5] * inv, acc[6] * inv, acc[7] * inv);
        float4* dst = (float4*)(agg + (size_t)d * DD + hl * 8);
        dst[0] = v0;
        dst[1] = v1;
    }
}

// ==================== f32x2 helpers ====================
__device__ __forceinline__ void fma2(u64& d, u64 a, u64 b) {
    asm("fma.rn.f32x2 %0, %1, %2, %0;" : "+l"(d) : "l"(a), "l"(b));
}
__device__ __forceinline__ u64 dup2(float x) {
    u64 r;
    asm("mov.b64 %0, {%1, %1};" : "=l"(r) : "r"(__float_as_uint(x)));
    return r;
}
__device__ __forceinline__ void unpk(float& lo, float& hi, u64 v) {
    unsigned a, b;
    asm("mov.b64 {%0, %1}, %2;" : "=r"(a), "=r"(b) : "l"(v));
    lo = __uint_as_float(a); hi = __uint_as_float(b);
}

// ==================== fused SAGE GEMM (8x8 blocking, conflict-free) ====================
#define GEMM_SMEM ((256 * 128 + 128 * 128) * sizeof(float))   // 192KB

__global__ void __launch_bounds__(256, 1)
sage_gemm(const float* __restrict__ mean, const float* __restrict__ h,
          const float* __restrict__ Wl, const float* __restrict__ Wr,
          const float* __restrict__ bias, float* __restrict__ out,
          __half* __restrict__ h16out, int n, int relu) {
    extern __shared__ float sm[];
    float* Wt = sm;                 // [256][128]
    float* As = sm + 256 * 128;     // [128][128]

    int tid = threadIdx.x;
    int row0 = blockIdx.x * 128;

    #pragma unroll
    for (int i = 0; i < 32; i++) {
        int fidx = i * 256 + tid;
        int j  = fidx & 127;
        int kk = (fidx >> 7) << 2;
        float4 v;
        if (kk < 128) v = __ldg((const float4*)(Wl + j * DD + kk));
        else          v = __ldg((const float4*)(Wr + j * DD + (kk - 128)));
        Wt[(kk + 0) * 128 + j] = v.x;
        Wt[(kk + 1) * 128 + j] = v.y;
        Wt[(kk + 2) * 128 + j] = v.z;
        Wt[(kk + 3) * 128 + j] = v.w;
    }

    int tx = tid & 15;
    int ty = tid >> 4;

    u64 acc2[4][8];
    #pragma unroll
    for (int p = 0; p < 4; p++)
        #pragma unroll
        for (int c = 0; c < 8; c++) acc2[p][c] = 0ull;

    #pragma unroll
    for (int pass = 0; pass < 2; pass++) {
        const float* A = pass ? h : mean;
        __syncthreads();
        #pragma unroll
        for (int i = 0; i < 16; i++) {
            int fidx = i * 256 + tid;
            int r = fidx & 127;
            int k = (fidx >> 7) << 2;
            int row = row0 + r;
            float4 v = make_float4(0.f, 0.f, 0.f, 0.f);
            if (row < n) v = __ldg((const float4*)(A + (size_t)row * DD + k));
            As[(k + 0) * 128 + r] = v.x;
            As[(k + 1) * 128 + r] = v.y;
            As[(k + 2) * 128 + r] = v.z;
            As[(k + 3) * 128 + r] = v.w;
        }
        __syncthreads();

        const float* WtP = Wt + pass * 128 * 128;
        #pragma unroll 4
        for (int k = 0; k < 128; k++) {
            float4 w0 = *(const float4*)(WtP + k * 128 + tx * 4);
            float4 w1 = *(const float4*)(WtP + k * 128 + 64 + tx * 4);
            u64 wp[8];
            wp[0] = dup2(w0.x); wp[1] = dup2(w0.y); wp[2] = dup2(w0.z); wp[3] = dup2(w0.w);
            wp[4] = dup2(w1.x); wp[5] = dup2(w1.y); wp[6] = dup2(w1.z); wp[7] = dup2(w1.w);
            ulonglong2 q0 = *(const ulonglong2*)(As + k * 128 + ty * 8);
            ulonglong2 q1 = *(const ulonglong2*)(As + k * 128 + ty * 8 + 4);
            u64 pr[4] = {q0.x, q0.y, q1.x, q1.y};
            #pragma unroll
            for (int p = 0; p < 4; p++) {
                #pragma unroll
                for (int c = 0; c < 8; c++) fma2(acc2[p][c], pr[p], wp[c]);
            }
        }
    }

    float4 bv0 = __ldg((const float4*)(bias + tx * 4));
    float4 bv1 = __ldg((const float4*)(bias + 64 + tx * 4));
    #pragma unroll
    for (int p = 0; p < 4; p++) {
        float lo[8], hi[8];
        #pragma unroll
        for (int c = 0; c < 8; c++) unpk(lo[c], hi[c], acc2[p][c]);
        #pragma unroll
        for (int half = 0; half < 2; half++) {
            int rr = row0 + ty * 8 + 2 * p + half;
            if (rr >= n) continue;
            float* src = half ? hi : lo;
            float4 o0 = make_float4(src[0] + bv0.x, src[1] + bv0.y, src[2] + bv0.z, src[3] + bv0.w);
            float4 o1 = make_float4(src[4] + bv1.x, src[5] + bv1.y, src[6] + bv1.z, src[7] + bv1.w);
            if (relu) {
                o0.x = fmaxf(o0.x, 0.f); o0.y = fmaxf(o0.y, 0.f);
                o0.z = fmaxf(o0.z, 0.f); o0.w = fmaxf(o0.w, 0.f);
                o1.x = fmaxf(o1.x, 0.f); o1.y = fmaxf(o1.y, 0.f);
                o1.z = fmaxf(o1.z, 0.f); o1.w = fmaxf(o1.w, 0.f);
            }
            *(float4*)(out + (size_t)rr * DD + tx * 4)      = o0;
            *(float4*)(out + (size_t)rr * DD + 64 + tx * 4) = o1;
            if (h16out) {
                __half2 a0 = __floats2half2_rn(o0.x, o0.y);
                __half2 b0 = __floats2half2_rn(o0.z, o0.w);
                __half2 a1 = __floats2half2_rn(o1.x, o1.y);
                __half2 b1 = __floats2half2_rn(o1.z, o1.w);
                *(uint2*)(h16out + (size_t)rr * DD + tx * 4) =
                    make_uint2(*(uint32_t*)&a0, *(uint32_t*)&b0);
                *(uint2*)(h16out + (size_t)rr * DD + 64 + tx * 4) =
                    make_uint2(*(uint32_t*)&a1, *(uint32_t*)&b1);
            }
        }
    }
}

// ==================== launch ====================
extern "C" void kernel_launch(void* const* d_in, const int* in_sizes, int n_in,
                              void* d_out, int out_size) {
    const float* x   = (const float*)d_in[0];
    const int*   ei  = (const int*)d_in[1];     // int32
    const float* W1l = (const float*)d_in[2];
    const float* W1r = (const float*)d_in[3];
    const float* W2l = (const float*)d_in[4];
    const float* W2r = (const float*)d_in[5];
    const float* W3l = (const float*)d_in[6];
    const float* W3r = (const float*)d_in[7];
    const float* b1  = (const float*)d_in[8];
    const float* b2  = (const float*)d_in[9];
    const float* b3  = (const float*)d_in[10];
    float* out = (float*)d_out;

    int n = in_sizes[0] / DD;
    long long E = (long long)in_sizes[1] / 2;

    float *agg, *h0, *h1;
    __half* h16;
    int *cnt, *cur, *incl, *bsum, *rowptr, *csr;
    cudaGetSymbolAddress((void**)&agg,    g_agg);
    cudaGetSymbolAddress((void**)&h0,     g_h0);
    cudaGetSymbolAddress((void**)&h1,     g_h1);
    cudaGetSymbolAddress((void**)&h16,    g_h16);
    cudaGetSymbolAddress((void**)&cnt,    g_cnt);
    cudaGetSymbolAddress((void**)&cur,    g_cur);
    cudaGetSymbolAddress((void**)&incl,   g_incl);
    cudaGetSymbolAddress((void**)&bsum,   g_bsum);
    cudaGetSymbolAddress((void**)&rowptr, g_rowptr);
    cudaGetSymbolAddress((void**)&csr,    g_csr);

    cudaFuncSetAttribute(sage_gemm, cudaFuncAttributeMaxDynamicSharedMemorySize,
                         (int)GEMM_SMEM);

    unsigned eblocks = (unsigned)((E + 255) / 256);
    int total4 = n * DD / 4;
    int nb = (n + SB - 1) / SB;

    conv16z_kernel<<<(total4 + 255) / 256, 256>>>(x, h16, cnt, cur, total4, n);
    deg_kernel<<<eblocks, 256>>>(ei + E, cnt, E);
    scan1<<<nb, SB>>>(cnt, incl, bsum, n);
    scan2<<<1, 512>>>(bsum, nb);
    scan3<<<(n + 255) / 256, 256>>>(incl, cnt, bsum, rowptr, n, (int)E);
    place_kernel<<<eblocks, 256>>>(ei, rowptr, cur, csr, E);

    int agg_blocks  = (n + 7) / 8;
    int gemm_blocks = (n + 127) / 128;

    // Layer 1
    agg_kernel<<<agg_blocks, 256>>>(h16, rowptr, csr, agg, n);
    sage_gemm<<<gemm_blocks, 256, GEMM_SMEM>>>(agg, x, W1l, W1r, b1, h0, h16, n, 1);
    // Layer 2
    agg_kernel<<<agg_blocks, 256>>>(h16, rowptr, csr, agg, n);
    sage_gemm<<<gemm_blocks, 256, GEMM_SMEM>>>(agg, h0, W2l, W2r, b2, h1, h16, n, 1);
    // Layer 3
    agg_kernel<<<agg_blocks, 256>>>(h16, rowptr, csr, agg, n);
    sage_gemm<<<gemm_blocks, 256, GEMM_SMEM>>>(agg, h1, W3l, W3r, b3, out, (__half*)0, n, 0);
}